// round 13
// baseline (speedup 1.0000x reference)
#include <cuda_runtime.h>
#include <math.h>

// CMPNN layer: fused edge pipeline + atomic aggregation + fused node pipeline.
// Shapes (fixed): N=50000, E=800000, ND=ED=64, HD=192.
//
// Inputs (metadata order):
//  0 node_feats [N,64]   1 edge_feats [E,64]   2 src [E] i32   3 dst [E] i32
//  4 W1e [192,192]  5 W1n [192,256]  6 b1 [192]  7 ln_g [192]  8 ln_b [192]
//  9 W2 [192,192] 10 b2 [192]
// 11 Wih_e [192,192] 12 Whh_e [192,64] 13 bih_e [192] 14 bhh_e [192]
// 15 Wih_a [192,192] 16 Whh_a [192,64] 17 bih_a [192] 18 bhh_a [192]
// 19 Wre [64,64] 20 bre [64] 21 Wra [64,64] 22 bra [64]
// Output: [update_nodes (N*64) | update_edges (E*64)] float32.

#define MAXN 50000
__device__ float g_aggsum[MAXN * 128];   // segment_sum of m = [h_src, e']
__device__ int   g_aggmax[MAXN * 128];   // segment_max, order-preserving int encoding

static __device__ __forceinline__ int enc_f2i(float v) {
    int iv = __float_as_int(v);
    return iv >= 0 ? iv : (iv ^ 0x7FFFFFFF);
}
static __device__ __forceinline__ float dec_i2f(int key) {
    int iv = key >= 0 ? key : (key ^ 0x7FFFFFFF);
    return __int_as_float(iv);
}

__global__ void init_agg_kernel(int total) {
    int i = blockIdx.x * blockDim.x + threadIdx.x;
    if (i < total) {
        g_aggsum[i] = 0.0f;
        g_aggmax[i] = INT_MIN;   // < enc(-inf); decodes to NaN -> treated as empty
    }
}

// ---------------------------------------------------------------------------
// Shared-memory tiled GEMM:  Cs[64][NC] = As[64][KTOT] @ Wg[NC][KTOT]^T + bias
// 256 threads as 16x16 grid; each thread owns a 4-row x (NC/16)-col register
// tile. Weights staged through smem in K-chunks of 64 (pitch 65, conflict-free).
// ---------------------------------------------------------------------------
template<int NC, int KTOT, int LDA, int LDC>
static __device__ __forceinline__ void gemm_tile(
    const float* __restrict__ Wg, const float* __restrict__ bias,
    const float* __restrict__ As, float* __restrict__ Cs, float* Ws,
    int tid, int tx, int ty)
{
    constexpr int NJ = NC / 16;
    float acc[4][NJ];
    #pragma unroll
    for (int i = 0; i < 4; i++)
        #pragma unroll
        for (int j = 0; j < NJ; j++) acc[i][j] = 0.0f;

    for (int k0 = 0; k0 < KTOT; k0 += 64) {
        for (int idx = tid; idx < NC * 64; idx += 256) {
            int col = idx >> 6, kk = idx & 63;
            Ws[col * 65 + kk] = Wg[col * KTOT + k0 + kk];
        }
        __syncthreads();
        const float* Ab = As + ty * 4 * LDA + k0;
        const float* Wb = Ws + tx * 65;
        #pragma unroll 4
        for (int kk = 0; kk < 64; ++kk) {
            float a[4];
            #pragma unroll
            for (int i = 0; i < 4; i++) a[i] = Ab[i * LDA + kk];
            #pragma unroll
            for (int j = 0; j < NJ; j++) {
                float w = Wb[j * 16 * 65 + kk];
                #pragma unroll
                for (int i = 0; i < 4; i++) acc[i][j] = fmaf(a[i], w, acc[i][j]);
            }
        }
        __syncthreads();
    }
    #pragma unroll
    for (int j = 0; j < NJ; j++) {
        float bv = bias[tx + 16 * j];
        #pragma unroll
        for (int i = 0; i < 4; i++)
            Cs[(ty * 4 + i) * LDC + tx + 16 * j] = acc[i][j] + bv;
    }
    __syncthreads();
}

// Small GEMM: acc[4][4] = As[64][64] @ Wg[64][64]^T, result left in registers.
template<int LDA>
static __device__ __forceinline__ void gemm64_reg(
    const float* __restrict__ Wg, const float* __restrict__ As,
    float* Ws, float acc[4][4], int tid, int tx, int ty)
{
    #pragma unroll
    for (int i = 0; i < 4; i++)
        #pragma unroll
        for (int j = 0; j < 4; j++) acc[i][j] = 0.0f;
    for (int idx = tid; idx < 64 * 64; idx += 256)
        Ws[(idx >> 6) * 65 + (idx & 63)] = Wg[idx];
    __syncthreads();
    const float* Ab = As + ty * 4 * LDA;
    const float* Wb = Ws + tx * 65;
    #pragma unroll 4
    for (int kk = 0; kk < 64; ++kk) {
        float a[4];
        #pragma unroll
        for (int i = 0; i < 4; i++) a[i] = Ab[i * LDA + kk];
        #pragma unroll
        for (int j = 0; j < 4; j++) {
            float w = Wb[j * 16 * 65 + kk];
            #pragma unroll
            for (int i = 0; i < 4; i++) acc[i][j] = fmaf(a[i], w, acc[i][j]);
        }
    }
    __syncthreads();
}

static __device__ __forceinline__ float sigm(float x) { return 1.0f / (1.0f + expf(-x)); }

// LayerNorm(192) + affine + LeakyReLU(0.2), in place on Bs (pitch 196).
static __device__ __forceinline__ void ln_leaky(
    float* Bs, float* muA, float* rsA,
    const float* __restrict__ lng, const float* __restrict__ lnb,
    int tid, int tx, int ty)
{
    if (tid < 64) {
        const float* row = Bs + tid * 196;
        float s = 0.0f, s2 = 0.0f;
        for (int k = 0; k < 192; k++) { float v = row[k]; s += v; s2 = fmaf(v, v, s2); }
        float mu = s * (1.0f / 192.0f);
        float var = s2 * (1.0f / 192.0f) - mu * mu;
        muA[tid] = mu;
        rsA[tid] = rsqrtf(var + 1e-5f);
    }
    __syncthreads();
    #pragma unroll
    for (int i = 0; i < 4; i++) {
        int r = ty * 4 + i;
        float mu = muA[r], rs = rsA[r];
        #pragma unroll
        for (int j = 0; j < 12; j++) {
            int c = tx + 16 * j;
            float v = Bs[r * 196 + c];
            v = (v - mu) * rs * lng[c] + lnb[c];
            Bs[r * 196 + c] = v > 0.0f ? v : 0.2f * v;
        }
    }
    __syncthreads();
}

// ---------------------------------------------------------------------------
// Edge pipeline: 64 edges / CTA
// smem floats: A[64*196] B[64*196] W[192*65] HE[64*132] mu[64] rs[64] src/dst[128]
// ---------------------------------------------------------------------------
#define EDGE_SMEM_FLOATS (12544 + 12544 + 12480 + 8448 + 64 + 64 + 128)

__global__ __launch_bounds__(256, 1) void edge_kernel(
    const float* __restrict__ nf, const float* __restrict__ ef,
    const int* __restrict__ src, const int* __restrict__ dst,
    const float* __restrict__ W1e, const float* __restrict__ b1,
    const float* __restrict__ lng, const float* __restrict__ lnb,
    const float* __restrict__ W2, const float* __restrict__ b2,
    const float* __restrict__ Wih, const float* __restrict__ Whh,
    const float* __restrict__ bih, const float* __restrict__ bhh,
    const float* __restrict__ Wre, const float* __restrict__ bre,
    float* __restrict__ out_edges, int E)
{
    extern __shared__ float sm[];
    float* A  = sm;                    // [64][196]
    float* B  = A + 64 * 196;          // [64][196]
    float* W  = B + 64 * 196;          // [192][65]
    float* HE = W + 192 * 65;          // [64][132]: cols 0:64 h_src, 64:128 e / e'
    float* muA = HE + 64 * 132;
    float* rsA = muA + 64;
    int* srcS = (int*)(rsA + 64);
    int* dstS = srcS + 64;

    const int tid = threadIdx.x, tx = tid & 15, ty = tid >> 4;
    const int eg0 = blockIdx.x * 64;

    if (tid < 64) {
        int e = eg0 + tid;
        srcS[tid] = e < E ? src[e] : 0;
        dstS[tid] = e < E ? dst[e] : 0;
    }
    __syncthreads();

    // Gather msg = [h_src, h_dst, edge_feats] into A; keep [h_src, e] in HE.
    const float4* nf4 = (const float4*)nf;
    const float4* ef4 = (const float4*)ef;
    for (int idx = tid; idx < 64 * 48; idx += 256) {
        int e = idx / 48, q = idx % 48;
        bool valid = (eg0 + e) < E;
        float4 v = make_float4(0.f, 0.f, 0.f, 0.f);
        if (q < 16) {
            if (valid) v = nf4[srcS[e] * 16 + q];
            ((float4*)(HE + e * 132))[q] = v;
        } else if (q < 32) {
            if (valid) v = nf4[dstS[e] * 16 + (q - 16)];
        } else {
            if (valid) v = ef4[(size_t)(eg0 + e) * 16 + (q - 32)];
            ((float4*)(HE + e * 132))[q - 16] = v;
        }
        ((float4*)(A + e * 196))[q] = v;
    }
    __syncthreads();

    // msg_booster: Linear -> LN -> LeakyReLU(0.2) -> Linear
    gemm_tile<192, 192, 196, 196>(W1e, b1, A, B, W, tid, tx, ty);
    ln_leaky(B, muA, rsA, lng, lnb, tid, tx, ty);
    gemm_tile<192, 192, 196, 196>(W2, b2, B, A, W, tid, tx, ty);   // A = edge_input
    // GRU gates
    gemm_tile<192, 192, 196, 196>(Wih, bih, A, B, W, tid, tx, ty); // B = gi
    gemm_tile<192,  64, 132, 196>(Whh, bhh, HE + 64, A, W, tid, tx, ty); // A = gh
    // residual edge_feats @ Wre^T
    float acc[4][4];
    gemm64_reg<132>(Wre, HE + 64, W, acc, tid, tx, ty);

    // GRU epilogue + residual + LeakyReLU(0.01); write e', stash in HE[64:128]
    #pragma unroll
    for (int i = 0; i < 4; i++) {
        int e = ty * 4 + i;
        bool valid = (eg0 + e) < E;
        #pragma unroll
        for (int j = 0; j < 4; j++) {
            int c = tx + 16 * j;
            float gir = B[e * 196 + c], giz = B[e * 196 + 64 + c], gin = B[e * 196 + 128 + c];
            float ghr = A[e * 196 + c], ghz = A[e * 196 + 64 + c], ghn = A[e * 196 + 128 + c];
            float efv = HE[e * 132 + 64 + c];
            float r = sigm(gir + ghr);
            float z = sigm(giz + ghz);
            float n = tanhf(fmaf(r, ghn, gin));
            float h = (1.0f - z) * n + z * efv;
            float res = h + acc[i][j] + bre[c];
            float ue = res > 0.0f ? res : 0.01f * res;
            if (valid) out_edges[(size_t)(eg0 + e) * 64 + c] = ue;
            HE[e * 132 + 64 + c] = ue;
        }
    }
    __syncthreads();

    // Aggregate m = [h_src, e'] at dst: sum + max.
    for (int idx = tid; idx < 64 * 128; idx += 256) {
        int e = idx >> 7, c = idx & 127;
        if ((eg0 + e) < E) {
            int d = dstS[e];
            float v = HE[e * 132 + c];
            atomicAdd(&g_aggsum[d * 128 + c], v);
            atomicMax(&g_aggmax[d * 128 + c], enc_f2i(v));
        }
    }
}

// ---------------------------------------------------------------------------
// Node pipeline: 64 nodes / CTA
// smem floats: A[64*260] B[64*196] W[192*65] NF[64*68] mu[64] rs[64]
// ---------------------------------------------------------------------------
#define NODE_SMEM_FLOATS (16640 + 12544 + 12480 + 4352 + 64 + 64)

__global__ __launch_bounds__(256, 1) void node_kernel(
    const float* __restrict__ nf,
    const float* __restrict__ W1n, const float* __restrict__ b1,
    const float* __restrict__ lng, const float* __restrict__ lnb,
    const float* __restrict__ W2, const float* __restrict__ b2,
    const float* __restrict__ Wih, const float* __restrict__ Whh,
    const float* __restrict__ bih, const float* __restrict__ bhh,
    const float* __restrict__ Wra, const float* __restrict__ bra,
    float* __restrict__ out_nodes, int N)
{
    extern __shared__ float sm[];
    float* A  = sm;                    // [64][260] : agg = [sum(128) | max(128)]
    float* B  = A + 64 * 260;          // [64][196]
    float* W  = B + 64 * 196;          // [192][65]
    float* NF = W + 192 * 65;          // [64][68]  : node_feats
    float* muA = NF + 64 * 68;
    float* rsA = muA + 64;

    const int tid = threadIdx.x, tx = tid & 15, ty = tid >> 4;
    const int n0 = blockIdx.x * 64;

    for (int idx = tid; idx < 64 * 128; idx += 256) {
        int r = idx >> 7, c = idx & 127;
        int n = n0 + r;
        float s = 0.0f, m = 0.0f;
        if (n < N) {
            s = g_aggsum[n * 128 + c];
            float dm = dec_i2f(g_aggmax[n * 128 + c]);
            m = isfinite(dm) ? dm : 0.0f;   // empty mailbox -> 0
        }
        A[r * 260 + c] = s;
        A[r * 260 + 128 + c] = m;
    }
    for (int idx = tid; idx < 64 * 64; idx += 256) {
        int r = idx >> 6, c = idx & 63;
        NF[r * 68 + c] = (n0 + r) < N ? nf[(size_t)(n0 + r) * 64 + c] : 0.0f;
    }
    __syncthreads();

    gemm_tile<192, 256, 260, 196>(W1n, b1, A, B, W, tid, tx, ty);
    ln_leaky(B, muA, rsA, lng, lnb, tid, tx, ty);
    gemm_tile<192, 192, 196, 260>(W2, b2, B, A, W, tid, tx, ty);   // A = node_input
    gemm_tile<192, 192, 260, 196>(Wih, bih, A, B, W, tid, tx, ty); // B = gi
    gemm_tile<192,  64,  68, 260>(Whh, bhh, NF, A, W, tid, tx, ty); // A = gh
    float acc[4][4];
    gemm64_reg<68>(Wra, NF, W, acc, tid, tx, ty);

    #pragma unroll
    for (int i = 0; i < 4; i++) {
        int e = ty * 4 + i;
        if ((n0 + e) >= N) continue;
        #pragma unroll
        for (int j = 0; j < 4; j++) {
            int c = tx + 16 * j;
            float gir = B[e * 196 + c], giz = B[e * 196 + 64 + c], gin = B[e * 196 + 128 + c];
            float ghr = A[e * 260 + c], ghz = A[e * 260 + 64 + c], ghn = A[e * 260 + 128 + c];
            float hv = NF[e * 68 + c];
            float r = sigm(gir + ghr);
            float z = sigm(giz + ghz);
            float n = tanhf(fmaf(r, ghn, gin));
            float h = (1.0f - z) * n + z * hv;
            float res = h + acc[i][j] + bra[c];
            out_nodes[(size_t)(n0 + e) * 64 + c] = res > 0.0f ? res : 0.01f * res;
        }
    }
}

extern "C" void kernel_launch(void* const* d_in, const int* in_sizes, int n_in,
                              void* d_out, int out_size)
{
    const float* nf   = (const float*)d_in[0];
    const float* ef   = (const float*)d_in[1];
    const int*   src  = (const int*)d_in[2];
    const int*   dst  = (const int*)d_in[3];
    const float* W1e  = (const float*)d_in[4];
    const float* W1n  = (const float*)d_in[5];
    const float* b1   = (const float*)d_in[6];
    const float* lng  = (const float*)d_in[7];
    const float* lnb  = (const float*)d_in[8];
    const float* W2   = (const float*)d_in[9];
    const float* b2   = (const float*)d_in[10];
    const float* Wih_e = (const float*)d_in[11];
    const float* Whh_e = (const float*)d_in[12];
    const float* bih_e = (const float*)d_in[13];
    const float* bhh_e = (const float*)d_in[14];
    const float* Wih_a = (const float*)d_in[15];
    const float* Whh_a = (const float*)d_in[16];
    const float* bih_a = (const float*)d_in[17];
    const float* bhh_a = (const float*)d_in[18];
    const float* Wre  = (const float*)d_in[19];
    const float* bre  = (const float*)d_in[20];
    const float* Wra  = (const float*)d_in[21];
    const float* bra  = (const float*)d_in[22];

    const int N = in_sizes[0] / 64;
    const int E = in_sizes[2];

    float* out_nodes = (float*)d_out;
    float* out_edges = out_nodes + (size_t)N * 64;

    const int edge_smem = EDGE_SMEM_FLOATS * 4;
    const int node_smem = NODE_SMEM_FLOATS * 4;
    cudaFuncSetAttribute(edge_kernel, cudaFuncAttributeMaxDynamicSharedMemorySize, edge_smem);
    cudaFuncSetAttribute(node_kernel, cudaFuncAttributeMaxDynamicSharedMemorySize, node_smem);

    int aggTotal = N * 128;
    init_agg_kernel<<<(aggTotal + 255) / 256, 256>>>(aggTotal);

    edge_kernel<<<(E + 63) / 64, 256, edge_smem>>>(
        nf, ef, src, dst, W1e, b1, lng, lnb, W2, b2,
        Wih_e, Whh_e, bih_e, bhh_e, Wre, bre, out_edges, E);

    node_kernel<<<(N + 63) / 64, 256, node_smem>>>(
        nf, W1n, b1, lng, lnb, W2, b2,
        Wih_a, Whh_a, bih_a, bhh_a, Wra, bra, out_nodes, N);
}

// round 14
// speedup vs baseline: 1.1821x; 1.1821x over previous
#include <cuda_runtime.h>
#include <math.h>

// CMPNN layer: fused edge pipeline + atomic aggregation + fused node pipeline.
// R14: packed fp32x2 FFMA2 inner loops (fma.rn.f32x2) -> 2x fp32 MAC throughput.
// Shapes (fixed): N=50000, E=800000, ND=ED=64, HD=192.
//
// Output: [update_nodes (N*64) | update_edges (E*64)] float32.

#define MAXN 50000
__device__ float g_aggsum[MAXN * 128];   // segment_sum of m = [h_src, e']
__device__ int   g_aggmax[MAXN * 128];   // segment_max, order-preserving int encoding

static __device__ __forceinline__ int enc_f2i(float v) {
    int iv = __float_as_int(v);
    return iv >= 0 ? iv : (iv ^ 0x7FFFFFFF);
}
static __device__ __forceinline__ float dec_i2f(int key) {
    int iv = key >= 0 ? key : (key ^ 0x7FFFFFFF);
    return __int_as_float(iv);
}

// ---- packed f32x2 helpers (Blackwell FFMA2 path; ptxas never emits these) ----
typedef unsigned long long u64t;

static __device__ __forceinline__ u64t bcast2(float x) {
    u64t r; asm("mov.b64 %0, {%1, %1};" : "=l"(r) : "f"(x)); return r;
}
static __device__ __forceinline__ void unpk2(float& lo, float& hi, u64t v) {
    asm("mov.b64 {%0, %1}, %2;" : "=f"(lo), "=f"(hi) : "l"(v));
}
#define FMA2(d, a, b, c) \
    asm("fma.rn.f32x2 %0, %1, %2, %3;" : "=l"(d) : "l"(a), "l"(b), "l"(c))

__global__ void init_agg_kernel(int total) {
    int i = blockIdx.x * blockDim.x + threadIdx.x;
    if (i < total) {
        g_aggsum[i] = 0.0f;
        g_aggmax[i] = INT_MIN;   // < enc(-inf); decodes to NaN -> treated as empty
    }
}

// ---------------------------------------------------------------------------
// Shared-memory tiled GEMM:  Cs[64][NC] = As[64][KTOT] @ Wg[NC][KTOT]^T + bias
// 256 threads as 16x16 grid. Thread (tx,ty) owns rows ty*4..+3 and column
// PAIRS {32p+2tx, 32p+2tx+1}, p=0..NC/32-1, accumulated in packed f32x2.
// Weights staged K-major in smem: Ws[kk][col], pitch NC+2 (2-way-conflict
// staging writes, conflict-free 8B reads).
// ---------------------------------------------------------------------------
template<int NC, int KTOT, int LDA, int LDC>
static __device__ __forceinline__ void gemm_tile(
    const float* __restrict__ Wg, const float* __restrict__ bias,
    const float* __restrict__ As, float* __restrict__ Cs, float* Ws,
    int tid, int tx, int ty)
{
    constexpr int NP = NC / 32;       // f32x2 pairs per thread
    constexpr int WP = NC + 2;        // Ws pitch in floats (even -> 8B aligned rows)
    u64t acc2[4][NP];
    #pragma unroll
    for (int i = 0; i < 4; i++)
        #pragma unroll
        for (int p = 0; p < NP; p++) acc2[i][p] = 0ull;

    for (int k0 = 0; k0 < KTOT; k0 += 64) {
        for (int idx = tid; idx < NC * 64; idx += 256) {
            int col = idx >> 6, kk = idx & 63;
            Ws[kk * WP + col] = Wg[col * KTOT + k0 + kk];
        }
        __syncthreads();
        const float* Ab = As + ty * 4 * LDA + k0;
        #pragma unroll 4
        for (int kk = 0; kk < 64; ++kk) {
            u64t a2[4];
            #pragma unroll
            for (int i = 0; i < 4; i++) a2[i] = bcast2(Ab[i * LDA + kk]);
            const u64t* Wr = (const u64t*)(Ws + kk * WP) + tx;
            #pragma unroll
            for (int p = 0; p < NP; p++) {
                u64t w2 = Wr[p * 16];
                #pragma unroll
                for (int i = 0; i < 4; i++) FMA2(acc2[i][p], a2[i], w2, acc2[i][p]);
            }
        }
        __syncthreads();
    }
    #pragma unroll
    for (int p = 0; p < NP; p++) {
        int c0 = 32 * p + 2 * tx;
        float b0 = bias[c0], b1v = bias[c0 + 1];
        #pragma unroll
        for (int i = 0; i < 4; i++) {
            float lo, hi; unpk2(lo, hi, acc2[i][p]);
            float* crow = Cs + (ty * 4 + i) * LDC + c0;
            crow[0] = lo + b0;
            crow[1] = hi + b1v;
        }
    }
    __syncthreads();
}

// Small GEMM: packed acc2[4][2] = As[64][64] @ Wg[64][64]^T, result in registers.
template<int LDA>
static __device__ __forceinline__ void gemm64_pair(
    const float* __restrict__ Wg, const float* __restrict__ As,
    float* Ws, u64t acc2[4][2], int tid, int tx, int ty)
{
    constexpr int WP = 66;
    #pragma unroll
    for (int i = 0; i < 4; i++)
        #pragma unroll
        for (int p = 0; p < 2; p++) acc2[i][p] = 0ull;
    for (int idx = tid; idx < 64 * 64; idx += 256)
        Ws[(idx & 63) * WP + (idx >> 6)] = Wg[idx];
    __syncthreads();
    const float* Ab = As + ty * 4 * LDA;
    #pragma unroll 4
    for (int kk = 0; kk < 64; ++kk) {
        u64t a2[4];
        #pragma unroll
        for (int i = 0; i < 4; i++) a2[i] = bcast2(Ab[i * LDA + kk]);
        const u64t* Wr = (const u64t*)(Ws + kk * WP) + tx;
        #pragma unroll
        for (int p = 0; p < 2; p++) {
            u64t w2 = Wr[p * 16];
            #pragma unroll
            for (int i = 0; i < 4; i++) FMA2(acc2[i][p], a2[i], w2, acc2[i][p]);
        }
    }
    __syncthreads();
}

static __device__ __forceinline__ float sigm(float x) { return 1.0f / (1.0f + expf(-x)); }

// LayerNorm(192) + affine + LeakyReLU(0.2), in place on Bs (pitch 196).
static __device__ __forceinline__ void ln_leaky(
    float* Bs, float* muA, float* rsA,
    const float* __restrict__ lng, const float* __restrict__ lnb,
    int tid, int tx, int ty)
{
    if (tid < 64) {
        const float* row = Bs + tid * 196;
        float s = 0.0f, s2 = 0.0f;
        for (int k = 0; k < 192; k++) { float v = row[k]; s += v; s2 = fmaf(v, v, s2); }
        float mu = s * (1.0f / 192.0f);
        float var = s2 * (1.0f / 192.0f) - mu * mu;
        muA[tid] = mu;
        rsA[tid] = rsqrtf(var + 1e-5f);
    }
    __syncthreads();
    #pragma unroll
    for (int i = 0; i < 4; i++) {
        int r = ty * 4 + i;
        float mu = muA[r], rs = rsA[r];
        #pragma unroll
        for (int p = 0; p < 6; p++) {
            #pragma unroll
            for (int l = 0; l < 2; l++) {
                int c = 32 * p + 2 * tx + l;
                float v = Bs[r * 196 + c];
                v = (v - mu) * rs * lng[c] + lnb[c];
                Bs[r * 196 + c] = v > 0.0f ? v : 0.2f * v;
            }
        }
    }
    __syncthreads();
}

// ---------------------------------------------------------------------------
// Edge pipeline: 64 edges / CTA
// smem floats: A[64*196] B[64*196] W[64*194] HE[64*132] mu[64] rs[64] src/dst[128]
// ---------------------------------------------------------------------------
#define EDGE_SMEM_FLOATS (12544 + 12544 + 12416 + 8448 + 64 + 64 + 128)

__global__ __launch_bounds__(256, 1) void edge_kernel(
    const float* __restrict__ nf, const float* __restrict__ ef,
    const int* __restrict__ src, const int* __restrict__ dst,
    const float* __restrict__ W1e, const float* __restrict__ b1,
    const float* __restrict__ lng, const float* __restrict__ lnb,
    const float* __restrict__ W2, const float* __restrict__ b2,
    const float* __restrict__ Wih, const float* __restrict__ Whh,
    const float* __restrict__ bih, const float* __restrict__ bhh,
    const float* __restrict__ Wre, const float* __restrict__ bre,
    float* __restrict__ out_edges, int E)
{
    extern __shared__ float sm[];
    float* A  = sm;                    // [64][196]
    float* B  = A + 64 * 196;          // [64][196]
    float* W  = B + 64 * 196;          // [64][194] K-major weight stage
    float* HE = W + 64 * 194;          // [64][132]: cols 0:64 h_src, 64:128 e / e'
    float* muA = HE + 64 * 132;
    float* rsA = muA + 64;
    int* srcS = (int*)(rsA + 64);
    int* dstS = srcS + 64;

    const int tid = threadIdx.x, tx = tid & 15, ty = tid >> 4;
    const int eg0 = blockIdx.x * 64;

    if (tid < 64) {
        int e = eg0 + tid;
        srcS[tid] = e < E ? src[e] : 0;
        dstS[tid] = e < E ? dst[e] : 0;
    }
    __syncthreads();

    // Gather msg = [h_src, h_dst, edge_feats] into A; keep [h_src, e] in HE.
    const float4* nf4 = (const float4*)nf;
    const float4* ef4 = (const float4*)ef;
    for (int idx = tid; idx < 64 * 48; idx += 256) {
        int e = idx / 48, q = idx % 48;
        bool valid = (eg0 + e) < E;
        float4 v = make_float4(0.f, 0.f, 0.f, 0.f);
        if (q < 16) {
            if (valid) v = nf4[srcS[e] * 16 + q];
            ((float4*)(HE + e * 132))[q] = v;
        } else if (q < 32) {
            if (valid) v = nf4[dstS[e] * 16 + (q - 16)];
        } else {
            if (valid) v = ef4[(size_t)(eg0 + e) * 16 + (q - 32)];
            ((float4*)(HE + e * 132))[q - 16] = v;
        }
        ((float4*)(A + e * 196))[q] = v;
    }
    __syncthreads();

    // msg_booster: Linear -> LN -> LeakyReLU(0.2) -> Linear
    gemm_tile<192, 192, 196, 196>(W1e, b1, A, B, W, tid, tx, ty);
    ln_leaky(B, muA, rsA, lng, lnb, tid, tx, ty);
    gemm_tile<192, 192, 196, 196>(W2, b2, B, A, W, tid, tx, ty);   // A = edge_input
    // GRU gates
    gemm_tile<192, 192, 196, 196>(Wih, bih, A, B, W, tid, tx, ty); // B = gi
    gemm_tile<192,  64, 132, 196>(Whh, bhh, HE + 64, A, W, tid, tx, ty); // A = gh
    // residual edge_feats @ Wre^T
    u64t accg[4][2];
    gemm64_pair<132>(Wre, HE + 64, W, accg, tid, tx, ty);

    // GRU epilogue + residual + LeakyReLU(0.01); write e', stash in HE[64:128]
    #pragma unroll
    for (int i = 0; i < 4; i++) {
        int e = ty * 4 + i;
        bool valid = (eg0 + e) < E;
        #pragma unroll
        for (int p = 0; p < 2; p++) {
            float rlo, rhi; unpk2(rlo, rhi, accg[i][p]);
            float rr[2] = {rlo, rhi};
            #pragma unroll
            for (int l = 0; l < 2; l++) {
                int c = 32 * p + 2 * tx + l;
                float gir = B[e * 196 + c], giz = B[e * 196 + 64 + c], gin = B[e * 196 + 128 + c];
                float ghr = A[e * 196 + c], ghz = A[e * 196 + 64 + c], ghn = A[e * 196 + 128 + c];
                float efv = HE[e * 132 + 64 + c];
                float r = sigm(gir + ghr);
                float z = sigm(giz + ghz);
                float n = tanhf(fmaf(r, ghn, gin));
                float h = (1.0f - z) * n + z * efv;
                float res = h + rr[l] + bre[c];
                float ue = res > 0.0f ? res : 0.01f * res;
                if (valid) out_edges[(size_t)(eg0 + e) * 64 + c] = ue;
                HE[e * 132 + 64 + c] = ue;
            }
        }
    }
    __syncthreads();

    // Aggregate m = [h_src, e'] at dst: sum + max.
    for (int idx = tid; idx < 64 * 128; idx += 256) {
        int e = idx >> 7, c = idx & 127;
        if ((eg0 + e) < E) {
            int d = dstS[e];
            float v = HE[e * 132 + c];
            atomicAdd(&g_aggsum[d * 128 + c], v);
            atomicMax(&g_aggmax[d * 128 + c], enc_f2i(v));
        }
    }
}

// ---------------------------------------------------------------------------
// Node pipeline: 64 nodes / CTA
// smem floats: A[64*260] B[64*196] W[64*194] NF[64*68] mu[64] rs[64]
// ---------------------------------------------------------------------------
#define NODE_SMEM_FLOATS (16640 + 12544 + 12416 + 4352 + 64 + 64)

__global__ __launch_bounds__(256, 1) void node_kernel(
    const float* __restrict__ nf,
    const float* __restrict__ W1n, const float* __restrict__ b1,
    const float* __restrict__ lng, const float* __restrict__ lnb,
    const float* __restrict__ W2, const float* __restrict__ b2,
    const float* __restrict__ Wih, const float* __restrict__ Whh,
    const float* __restrict__ bih, const float* __restrict__ bhh,
    const float* __restrict__ Wra, const float* __restrict__ bra,
    float* __restrict__ out_nodes, int N)
{
    extern __shared__ float sm[];
    float* A  = sm;                    // [64][260] : agg = [sum(128) | max(128)]
    float* B  = A + 64 * 260;          // [64][196]
    float* W  = B + 64 * 196;          // [64][194]
    float* NF = W + 64 * 194;          // [64][68]  : node_feats
    float* muA = NF + 64 * 68;
    float* rsA = muA + 64;

    const int tid = threadIdx.x, tx = tid & 15, ty = tid >> 4;
    const int n0 = blockIdx.x * 64;

    for (int idx = tid; idx < 64 * 128; idx += 256) {
        int r = idx >> 7, c = idx & 127;
        int n = n0 + r;
        float s = 0.0f, m = 0.0f;
        if (n < N) {
            s = g_aggsum[n * 128 + c];
            float dm = dec_i2f(g_aggmax[n * 128 + c]);
            m = isfinite(dm) ? dm : 0.0f;   // empty mailbox -> 0
        }
        A[r * 260 + c] = s;
        A[r * 260 + 128 + c] = m;
    }
    for (int idx = tid; idx < 64 * 64; idx += 256) {
        int r = idx >> 6, c = idx & 63;
        NF[r * 68 + c] = (n0 + r) < N ? nf[(size_t)(n0 + r) * 64 + c] : 0.0f;
    }
    __syncthreads();

    gemm_tile<192, 256, 260, 196>(W1n, b1, A, B, W, tid, tx, ty);
    ln_leaky(B, muA, rsA, lng, lnb, tid, tx, ty);
    gemm_tile<192, 192, 196, 260>(W2, b2, B, A, W, tid, tx, ty);   // A = node_input
    gemm_tile<192, 192, 260, 196>(Wih, bih, A, B, W, tid, tx, ty); // B = gi
    gemm_tile<192,  64,  68, 260>(Whh, bhh, NF, A, W, tid, tx, ty); // A = gh
    u64t accg[4][2];
    gemm64_pair<68>(Wra, NF, W, accg, tid, tx, ty);

    #pragma unroll
    for (int i = 0; i < 4; i++) {
        int e = ty * 4 + i;
        if ((n0 + e) >= N) continue;
        #pragma unroll
        for (int p = 0; p < 2; p++) {
            float rlo, rhi; unpk2(rlo, rhi, accg[i][p]);
            float rr[2] = {rlo, rhi};
            #pragma unroll
            for (int l = 0; l < 2; l++) {
                int c = 32 * p + 2 * tx + l;
                float gir = B[e * 196 + c], giz = B[e * 196 + 64 + c], gin = B[e * 196 + 128 + c];
                float ghr = A[e * 260 + c], ghz = A[e * 260 + 64 + c], ghn = A[e * 260 + 128 + c];
                float hv = NF[e * 68 + c];
                float r = sigm(gir + ghr);
                float z = sigm(giz + ghz);
                float n = tanhf(fmaf(r, ghn, gin));
                float h = (1.0f - z) * n + z * hv;
                float res = h + rr[l] + bra[c];
                out_nodes[(size_t)(n0 + e) * 64 + c] = res > 0.0f ? res : 0.01f * res;
            }
        }
    }
}

extern "C" void kernel_launch(void* const* d_in, const int* in_sizes, int n_in,
                              void* d_out, int out_size)
{
    const float* nf   = (const float*)d_in[0];
    const float* ef   = (const float*)d_in[1];
    const int*   src  = (const int*)d_in[2];
    const int*   dst  = (const int*)d_in[3];
    const float* W1e  = (const float*)d_in[4];
    const float* W1n  = (const float*)d_in[5];
    const float* b1   = (const float*)d_in[6];
    const float* lng  = (const float*)d_in[7];
    const float* lnb  = (const float*)d_in[8];
    const float* W2   = (const float*)d_in[9];
    const float* b2   = (const float*)d_in[10];
    const float* Wih_e = (const float*)d_in[11];
    const float* Whh_e = (const float*)d_in[12];
    const float* bih_e = (const float*)d_in[13];
    const float* bhh_e = (const float*)d_in[14];
    const float* Wih_a = (const float*)d_in[15];
    const float* Whh_a = (const float*)d_in[16];
    const float* bih_a = (const float*)d_in[17];
    const float* bhh_a = (const float*)d_in[18];
    const float* Wre  = (const float*)d_in[19];
    const float* bre  = (const float*)d_in[20];
    const float* Wra  = (const float*)d_in[21];
    const float* bra  = (const float*)d_in[22];

    const int N = in_sizes[0] / 64;
    const int E = in_sizes[2];

    float* out_nodes = (float*)d_out;
    float* out_edges = out_nodes + (size_t)N * 64;

    const int edge_smem = EDGE_SMEM_FLOATS * 4;
    const int node_smem = NODE_SMEM_FLOATS * 4;
    cudaFuncSetAttribute(edge_kernel, cudaFuncAttributeMaxDynamicSharedMemorySize, edge_smem);
    cudaFuncSetAttribute(node_kernel, cudaFuncAttributeMaxDynamicSharedMemorySize, node_smem);

    int aggTotal = N * 128;
    init_agg_kernel<<<(aggTotal + 255) / 256, 256>>>(aggTotal);

    edge_kernel<<<(E + 63) / 64, 256, edge_smem>>>(
        nf, ef, src, dst, W1e, b1, lng, lnb, W2, b2,
        Wih_e, Whh_e, bih_e, bhh_e, Wre, bre, out_edges, E);

    node_kernel<<<(N + 63) / 64, 256, node_smem>>>(
        nf, W1n, b1, lng, lnb, W2, b2,
        Wih_a, Whh_a, bih_a, bhh_a, Wra, bra, out_nodes, N);
}